// round 15
// baseline (speedup 1.0000x reference)
#include <cuda_runtime.h>
#include <cuda_bf16.h>
#include <math.h>

#define MAXN 10000
#define MAXE 320000

// ---------------- scratch (device globals; no runtime alloc) ----------------
__device__ float g_s  [MAXN*32];
__device__ float g_v  [MAXN*96];    // (N,3,32)
__device__ float g_scs[MAXN*32];
__device__ float g_scv[MAXN*96];
__device__ __nv_bfloat16 g_xsb[MAXN*32];   // bf16 features for gather
__device__ __nv_bfloat16 g_xvb[MAXN*96];
__device__ float g_aggs[MAXN*64];
__device__ float g_aggv[MAXN*192];
// CSR (by dst) + permuted edge data
__device__ int   g_deg   [MAXN];     // zero-initialized; restored to 0 by k_read
__device__ int   g_cursor[MAXN];
__device__ int   g_rowstart[MAXN+1];
__device__ int   g_srcP  [MAXE];
__device__ int   g_invP  [MAXE];
__device__ float g_YP    [MAXE*3];
// per-edge radial weights, bf16, double-buffered per layer
__device__ __nv_bfloat16 g_wb0[MAXE*128];
__device__ __nv_bfloat16 g_wb1[MAXE*128];
// Wfc2 preconverted to bf16 (both layers)
__device__ __nv_bfloat16 g_w2b[16384];

// ---------------- constants ----------------
#define SQRT3F   1.7320508075688772f
#define ISQRT3F  0.5773502691896258f
#define INV_NB   0.17677669529663687f
#define NORM128  0.08838834764831845f
#define NORM256  0.0625f
#define INVS10   0.3162277660168379f
#define C_S      0.3826834323650898f
#define C_X      0.9238795325112867f
#define PI_F     3.14159265358979f
#define WG_TE    128
#define FUSED_SMEM 65536
#define HB_STR   72     // shHb row stride in bf16 (144 B)
#define W2_STR   136    // shW2b row stride in bf16 (272 B)

typedef unsigned long long ull;

// ---------------- packed f32x2 helpers ----------------
__device__ __forceinline__ ull pack2(float lo, float hi) {
    ull r;
    asm("mov.b64 %0, {%1, %2};" : "=l"(r) : "f"(lo), "f"(hi));
    return r;
}
__device__ __forceinline__ void ffma2(ull& acc, ull a, ull b) {
    asm("fma.rn.f32x2 %0, %1, %2, %0;" : "+l"(acc) : "l"(a), "l"(b));
}
__device__ __forceinline__ ull mul2r(ull a, ull b) {
    ull r;
    asm("mul.rn.f32x2 %0, %1, %2;" : "=l"(r) : "l"(a), "l"(b));
    return r;
}
__device__ __forceinline__ float2 unpack2(ull v) {
    float2 f;
    asm("mov.b64 {%0, %1}, %2;" : "=f"(f.x), "=f"(f.y) : "l"(v));
    return f;
}
__device__ __forceinline__ unsigned int bf16x2_of(float a, float b) {
    unsigned int r;
    asm("cvt.rn.bf16x2.f32 %0, %1, %2;" : "=r"(r) : "f"(b), "f"(a));
    return r;
}
__device__ __forceinline__ unsigned int sptr(const void* p) {
    return (unsigned int)__cvta_generic_to_shared(p);
}
__device__ __forceinline__ void mma16816(float* d, const unsigned* a,
                                         unsigned b0, unsigned b1) {
    asm volatile(
        "mma.sync.aligned.m16n8k16.row.col.f32.bf16.bf16.f32 "
        "{%0,%1,%2,%3}, {%4,%5,%6,%7}, {%8,%9}, {%0,%1,%2,%3};"
        : "+f"(d[0]), "+f"(d[1]), "+f"(d[2]), "+f"(d[3])
        : "r"(a[0]), "r"(a[1]), "r"(a[2]), "r"(a[3]), "r"(b0), "r"(b1));
}

// ---------------- tiny preconversion ----------------
__global__ void k_cvt(const float* __restrict__ Wfc2) {
    int i = blockIdx.x * blockDim.x + threadIdx.x;
    if (i < 16384) g_w2b[i] = __float2bfloat16(Wfc2[i]);
}

// ---------------- CSR build ----------------
__global__ void k_hist(const int* __restrict__ edst, int E) {
    int e = blockIdx.x * blockDim.x + threadIdx.x;
    if (e < E) atomicAdd(&g_deg[edst[e]], 1);
}
#define SCAN_T 1024
__global__ void k_scan(int N) {
    __shared__ int sums[SCAN_T];
    int t = threadIdx.x;
    int IT = (N + SCAN_T - 1) / SCAN_T;
    int lo = t * IT, hi = lo + IT; if (hi > N) hi = N; if (lo > N) lo = N;
    int s = 0;
    for (int i = lo; i < hi; i++) s += g_deg[i];
    sums[t] = s;
    __syncthreads();
    for (int off = 1; off < SCAN_T; off <<= 1) {
        int v = (t >= off) ? sums[t - off] : 0;
        __syncthreads();
        sums[t] += v;
        __syncthreads();
    }
    int run = (t == 0) ? 0 : sums[t - 1];
    for (int i = lo; i < hi; i++) {
        g_rowstart[i] = run;
        g_cursor[i]   = run;
        run += g_deg[i];
    }
    if (hi == N) g_rowstart[N] = run;
}
__global__ void k_fill(const int* __restrict__ esrc, const int* __restrict__ edst, int E) {
    int e = blockIdx.x * blockDim.x + threadIdx.x;
    if (e >= E) return;
    int pos = atomicAdd(&g_cursor[edst[e]], 1);
    g_srcP[pos] = esrc[e];
    g_invP[pos] = e;
}

// ================= device bodies ======================

// --- fctp1: packed f32x2; writes bf16 features for the gather ---
__device__ void fctp1_dev(float* sm, const float* __restrict__ attr,
                          const float* __restrict__ xin,
                          const float* __restrict__ W0, const float* __restrict__ W1,
                          const float* __restrict__ L0, const float* __restrict__ L1,
                          int N, int relBid, int nBlocks) {
    float2* sW02 = (float2*)sm;
    float2* sW12 = (float2*)(sm + 8192);
    for (int i = threadIdx.x; i < 4096; i += 256) {
        sW02[i] = make_float2(W0[i], L0[i]);
        sW12[i] = make_float2(W1[i], L1[i]);
    }
    __syncthreads();
    const ull* w02 = (const ull*)sW02;
    const ull* w12 = (const ull*)sW12;
    int lane = threadIdx.x & 31;
    int wid  = relBid * 8 + (threadIdx.x >> 5);
    int wstr = nBlocks * 8;
    for (int n = wid; n < N; n += wstr) {
        float sl, v0, v1, v2;
        if (xin) {
            sl = xin[n*128 + lane];
            v0 = xin[n*128 + 32 + lane*3 + 0];
            v1 = xin[n*128 + 32 + lane*3 + 1];
            v2 = xin[n*128 + 32 + lane*3 + 2];
            g_s[n*32+lane]      = sl;
            g_v[n*96+lane]      = v0;
            g_v[n*96+32+lane]   = v1;
            g_v[n*96+64+lane]   = v2;
        } else {
            sl = g_s[n*32 + lane];
            v0 = g_v[n*96 + lane];
            v1 = g_v[n*96 + 32 + lane];
            v2 = g_v[n*96 + 64 + lane];
        }
        ull atp[4];
#pragma unroll
        for (int a = 0; a < 4; a++) { float av = attr[n*4+a]; atp[a] = pack2(av, av); }
        ull accS = 0ull, accV0 = 0ull, accV1 = 0ull, accV2 = 0ull;
        for (int u = 0; u < 32; u++) {
            float su  = __shfl_sync(0xffffffffu, sl, u);
            float vu0 = __shfl_sync(0xffffffffu, v0, u);
            float vu1 = __shfl_sync(0xffffffffu, v1, u);
            float vu2 = __shfl_sync(0xffffffffu, v2, u);
            ull sup = pack2(su, su);
            ull v0p = pack2(vu0, vu0);
            ull v1p = pack2(vu1, vu1);
            ull v2p = pack2(vu2, vu2);
            int base = u*128 + lane;
#pragma unroll
            for (int a = 0; a < 4; a++) {
                int wi = base + a*32;
                ull wa = w02[wi];
                ull wb = w12[wi];
                ffma2(accS,  mul2r(sup, atp[a]), wa);
                ffma2(accV0, mul2r(v0p, atp[a]), wb);
                ffma2(accV1, mul2r(v1p, atp[a]), wb);
                ffma2(accV2, mul2r(v2p, atp[a]), wb);
            }
        }
        float2 fS  = unpack2(accS);
        float2 fV0 = unpack2(accV0);
        float2 fV1 = unpack2(accV1);
        float2 fV2 = unpack2(accV2);
        g_scs[n*32+lane] = fS.x*NORM128;
        g_xsb[n*32+lane] = __float2bfloat16(fS.y*NORM128);
        g_scv[n*96+lane]      = fV0.x*NORM128;
        g_scv[n*96+32+lane]   = fV1.x*NORM128;
        g_scv[n*96+64+lane]   = fV2.x*NORM128;
        g_xvb[n*96+lane]      = __float2bfloat16(fV0.y*NORM128);
        g_xvb[n*96+32+lane]   = __float2bfloat16(fV1.y*NORM128);
        g_xvb[n*96+64+lane]   = __float2bfloat16(fV2.y*NORM128);
    }
}

// --- wgemm: 128-edge tile; h,W2 bf16 smem; h@W2 on tensor pipe ---
__device__ void wgemm_dev(float* sm, const float* __restrict__ evec,
                          const float* __restrict__ Wfc1, int w2off,
                          __nv_bfloat16* __restrict__ wout, int E, int bid,
                          int writeY) {
    float* shW1  = sm;                              // 640 f
    float* shEmb = sm + 640;                        // 1280 f
    __nv_bfloat16* shW2b = (__nv_bfloat16*)(sm + 1920);         // 64 x 136 bf16
    __nv_bfloat16* shHb  = (__nv_bfloat16*)(sm + 1920 + 4352);  // 128 x 72 bf16
    int tid = threadIdx.x;
    int eg0 = bid * WG_TE;
    int nE = E - eg0; if (nE > WG_TE) nE = WG_TE;

    for (int i = tid; i < 640; i += 256) shW1[i] = Wfc1[i];
    // W2 staged from preconverted bf16 with 16B copies
    {
        const uint4* src = (const uint4*)(g_w2b + w2off);   // 1024 uint4
        for (int i = tid; i < 1024; i += 256) {
            int k = i >> 4, c = i & 15;
            *(uint4*)&shW2b[k*W2_STR + c*8] = src[i];
        }
    }
    if (tid < WG_TE) {
        if (tid < nE) {
            int p = eg0 + tid;
            int e = g_invP[p];
            float vx = evec[e*3+0], vy = evec[e*3+1], vz = evec[e*3+2];
            float len = sqrtf(vx*vx + vy*vy + vz*vz);
            if (writeY) {
                float inv = 1.0f / (len + 1e-9f);
                g_YP[p*3+0] = SQRT3F * vx * inv;
                g_YP[p*3+1] = SQRT3F * vy * inv;
                g_YP[p*3+2] = SQRT3F * vz * inv;
            }
            float uu = 0.5f*len - 2.0f;
            float cut;
            if (uu > 0.0f)       cut = 0.0f;
            else if (uu < -1.0f) cut = 1.0f;
            else                 cut = (1.0f - __cosf(PI_F * uu)) * 0.5f;
#pragma unroll
            for (int b = 0; b < 10; b++) {
                float c = (4.0f/9.0f) * (float)b;
                float d = (len - c) * 2.5f;
                shEmb[tid*10+b] = __expf(-d*d) * cut;
            }
        } else {
#pragma unroll
            for (int b = 0; b < 10; b++) shEmb[tid*10+b] = 0.f;
        }
    }
    __syncthreads();

    for (int idx = tid; idx < WG_TE*64; idx += 256) {
        int e = idx >> 6, k = idx & 63;
        float acc = 0.f;
#pragma unroll
        for (int b = 0; b < 10; b++) acc += shEmb[e*10+b] * shW1[b*64+k];
        acc *= INVS10;
        shHb[e*HB_STR + k] = __float2bfloat16(acc / (1.0f + __expf(-acc)));
    }
    __syncthreads();

    int lane = tid & 31;
    int warp = tid >> 5;
    int eb = (warp & 3) * 32;
    int nb = (warp >> 2) * 64;

    unsigned a[2][4][4];
    {
        int r  = lane & 15;
        int cA = (lane >> 4) << 3;
#pragma unroll
        for (int mt = 0; mt < 2; mt++)
#pragma unroll
            for (int kc = 0; kc < 4; kc++) {
                unsigned ad = sptr(&shHb[(eb + mt*16 + r)*HB_STR + kc*16 + cA]);
                asm volatile(
                    "ldmatrix.sync.aligned.m8n8.x4.shared.b16 {%0,%1,%2,%3}, [%4];"
                    : "=r"(a[mt][kc][0]), "=r"(a[mt][kc][1]),
                      "=r"(a[mt][kc][2]), "=r"(a[mt][kc][3])
                    : "r"(ad));
            }
    }

    int row  = lane >> 2;
    int colp = (lane & 3) * 2;
#pragma unroll
    for (int nt = 0; nt < 8; nt++) {
        float acc0[4] = {0.f, 0.f, 0.f, 0.f};
        float acc1[4] = {0.f, 0.f, 0.f, 0.f};
#pragma unroll
        for (int kc = 0; kc < 4; kc++) {
            int rk = lane & 15;
            unsigned bd = sptr(&shW2b[(kc*16 + rk)*W2_STR + nb + nt*8]);
            unsigned b0, b1;
            asm volatile(
                "ldmatrix.sync.aligned.m8n8.x2.trans.shared.b16 {%0,%1}, [%2];"
                : "=r"(b0), "=r"(b1) : "r"(bd));
            mma16816(acc0, a[0][kc], b0, b1);
            mma16816(acc1, a[1][kc], b0, b1);
        }
        int col = nb + nt*8 + colp;
        int geA = eg0 + eb + row;
        int geB = geA + 8;
        int geC = geA + 16;
        int geD = geA + 24;
        if (geA < E)
            *(unsigned*)&wout[(size_t)geA*128 + col] = bf16x2_of(acc0[0]*0.125f, acc0[1]*0.125f);
        if (geB < E)
            *(unsigned*)&wout[(size_t)geB*128 + col] = bf16x2_of(acc0[2]*0.125f, acc0[3]*0.125f);
        if (geC < E)
            *(unsigned*)&wout[(size_t)geC*128 + col] = bf16x2_of(acc1[0]*0.125f, acc1[1]*0.125f);
        if (geD < E)
            *(unsigned*)&wout[(size_t)geD*128 + col] = bf16x2_of(acc1[2]*0.125f, acc1[3]*0.125f);
    }
}

// --- fctp2: packed f32x2 + gated state update ---
__device__ void fctp2_dev(float* sm, const float* __restrict__ attr,
                          const float* __restrict__ W20, const float* __restrict__ W21,
                          int N, int relBid, int nBlocks) {
    float2* sWp = (float2*)sm;
    for (int i = threadIdx.x; i < 8192; i += 256)
        sWp[i] = make_float2(W20[i], W21[i]);
    __syncthreads();
    const ull* wPair = (const ull*)sWp;
    int lane = threadIdx.x & 31;
    int wid  = relBid * 8 + (threadIdx.x >> 5);
    int wstr = nBlocks * 8;
    for (int n = wid; n < N; n += wstr) {
        float sa  = g_aggs[n*64 + lane],        sb  = g_aggs[n*64 + 32 + lane];
        float va0 = g_aggv[n*192 + lane],       vb0 = g_aggv[n*192 + 32 + lane];
        float va1 = g_aggv[n*192 + 64 + lane],  vb1 = g_aggv[n*192 + 96 + lane];
        float va2 = g_aggv[n*192 + 128 + lane], vb2 = g_aggv[n*192 + 160 + lane];
        ull atp[4];
#pragma unroll
        for (int a = 0; a < 4; a++) { float av = attr[n*4+a]; atp[a] = pack2(av, av); }
        ull accA = 0ull;
        ull accB = 0ull;
#pragma unroll 1
        for (int half = 0; half < 2; half++) {
            float ss  = half ? sb  : sa;
            float vv0 = half ? vb0 : va0;
            float vv1 = half ? vb1 : va1;
            float vv2 = half ? vb2 : va2;
            int uoff = half ? 32 : 0;
            for (int u = 0; u < 32; u++) {
                float su = __shfl_sync(0xffffffffu, ss,  u);
                float w0 = __shfl_sync(0xffffffffu, vv0, u);
                float w1 = __shfl_sync(0xffffffffu, vv1, u);
                float w2 = __shfl_sync(0xffffffffu, vv2, u);
                ull pA = pack2(su, w2);
                ull pB = pack2(w0, w1);
                int base = (u + uoff)*128 + lane;
#pragma unroll
                for (int a = 0; a < 4; a++) {
                    int wi = base + a*32;
                    ull wp = wPair[wi];
                    float2 wf = unpack2(wp);
                    ull wdup = pack2(wf.y, wf.y);
                    ffma2(accA, mul2r(pA, atp[a]), wp);
                    ffma2(accB, mul2r(pB, atp[a]), wdup);
                }
            }
        }
        float2 fA = unpack2(accA);
        float2 fB = unpack2(accB);
        float os  = fA.x*NORM256, ov2 = fA.y*NORM256;
        float ov0 = fB.x*NORM256, ov1 = fB.y*NORM256;
        float sn  = C_S * g_scs[n*32+lane] + C_X * os;
        float sig = 1.0f / (1.0f + __expf(-sn));
        g_s[n*32+lane] += sn * sig;
        float vn0 = C_S * g_scv[n*96+lane]      + C_X * ov0;
        float vn1 = C_S * g_scv[n*96+32+lane]   + C_X * ov1;
        float vn2 = C_S * g_scv[n*96+64+lane]   + C_X * ov2;
        g_v[n*96+lane]      += vn0 * sig;
        g_v[n*96+32+lane]   += vn1 * sig;
        g_v[n*96+64+lane]   += vn2 * sig;
    }
}

// ================= gather: dual streams, bf16 features =========
template<int BUF>
__global__ void __launch_bounds__(256)
k_gather(int N) {
    const __nv_bfloat16* __restrict__ win = BUF ? g_wb1 : g_wb0;
    int tid = threadIdx.x;
    int n = blockIdx.x*2 + (tid >> 7);
    if (n >= N) return;
    int sub = tid & 127;
    int k = sub >> 5, u = sub & 31;
    int t0 = g_rowstart[n], t1 = g_rowstart[n+1];
    int len  = t1 - t0;
    int hlen = (len + 1) >> 1;
    int tB0  = t0 + hlen;
    float a0 = 0.f, a1 = 0.f, a2 = 0.f;
    float b0 = 0.f, b1 = 0.f, b2 = 0.f;

    if (k == 0) {
        for (int i = 0; i < hlen; i++) {
            int eA = t0 + i, eB = tB0 + i;
            bool vB = (eB < t1);
            int sA = g_srcP[eA];
            int sB = vB ? g_srcP[eB] : 0;
            float wA = __bfloat162float(win[(size_t)eA*128 + u]);
            float wB = vB ? __bfloat162float(win[(size_t)eB*128 + u]) : 0.f;
            a0 += wA * __bfloat162float(g_xsb[sA*32 + u]);
            b0 += wB * __bfloat162float(g_xsb[sB*32 + u]);
        }
        g_aggs[n*64 + u] = (a0 + b0) * INV_NB;
    } else if (k == 1) {
        for (int i = 0; i < hlen; i++) {
            int eA = t0 + i, eB = tB0 + i;
            bool vB = (eB < t1);
            int sA = g_srcP[eA];
            int sB = vB ? g_srcP[eB] : 0;
            float wA = __bfloat162float(win[(size_t)eA*128 + 32 + u]);
            float wB = vB ? __bfloat162float(win[(size_t)eB*128 + 32 + u]) : 0.f;
            float dA = g_YP[eA*3+0]*__bfloat162float(g_xvb[sA*96+u])
                     + g_YP[eA*3+1]*__bfloat162float(g_xvb[sA*96+32+u])
                     + g_YP[eA*3+2]*__bfloat162float(g_xvb[sA*96+64+u]);
            float dB = g_YP[eB < t1 ? eB*3+0 : 0]*__bfloat162float(g_xvb[sB*96+u])
                     + g_YP[eB < t1 ? eB*3+1 : 0]*__bfloat162float(g_xvb[sB*96+32+u])
                     + g_YP[eB < t1 ? eB*3+2 : 0]*__bfloat162float(g_xvb[sB*96+64+u]);
            a0 += wA * dA;
            b0 += wB * dB;
        }
        g_aggs[n*64 + 32 + u] = (a0 + b0) * ISQRT3F * INV_NB;
    } else if (k == 2) {
        for (int i = 0; i < hlen; i++) {
            int eA = t0 + i, eB = tB0 + i;
            bool vB = (eB < t1);
            int sA = g_srcP[eA];
            int sB = vB ? g_srcP[eB] : 0;
            float wA = __bfloat162float(win[(size_t)eA*128 + 64 + u]);
            float wB = vB ? __bfloat162float(win[(size_t)eB*128 + 64 + u]) : 0.f;
            float mA = wA * __bfloat162float(g_xsb[sA*32 + u]);
            float mB = wB * __bfloat162float(g_xsb[sB*32 + u]);
            a0 += mA * g_YP[eA*3+0];
            a1 += mA * g_YP[eA*3+1];
            a2 += mA * g_YP[eA*3+2];
            int eBs = vB ? eB : eA;
            b0 += mB * g_YP[eBs*3+0];
            b1 += mB * g_YP[eBs*3+1];
            b2 += mB * g_YP[eBs*3+2];
        }
        g_aggv[n*192 +       u] = (a0 + b0) * INV_NB;
        g_aggv[n*192 +  64 + u] = (a1 + b1) * INV_NB;
        g_aggv[n*192 + 128 + u] = (a2 + b2) * INV_NB;
    } else {
        for (int i = 0; i < hlen; i++) {
            int eA = t0 + i, eB = tB0 + i;
            bool vB = (eB < t1);
            int sA = g_srcP[eA];
            int sB = vB ? g_srcP[eB] : 0;
            float wA = __bfloat162float(win[(size_t)eA*128 + 96 + u]);
            float wB = vB ? __bfloat162float(win[(size_t)eB*128 + 96 + u]) : 0.f;
            a0 += wA * __bfloat162float(g_xvb[sA*96 + u]);
            a1 += wA * __bfloat162float(g_xvb[sA*96 + 32 + u]);
            a2 += wA * __bfloat162float(g_xvb[sA*96 + 64 + u]);
            b0 += wB * __bfloat162float(g_xvb[sB*96 + u]);
            b1 += wB * __bfloat162float(g_xvb[sB*96 + 32 + u]);
            b2 += wB * __bfloat162float(g_xvb[sB*96 + 64 + u]);
        }
        g_aggv[n*192 +  32 + u] = (a0 + b0) * INV_NB;
        g_aggv[n*192 +  96 + u] = (a1 + b1) * INV_NB;
        g_aggv[n*192 + 160 + u] = (a2 + b2) * INV_NB;
    }
}

// ================= launches ======================

__global__ void __launch_bounds__(256, 3)
k_fusedA(const float* __restrict__ attr, const float* __restrict__ x,
         const float* __restrict__ evec,
         const float* __restrict__ W0, const float* __restrict__ W1,
         const float* __restrict__ L0, const float* __restrict__ L1,
         const float* __restrict__ Wfc1,
         int N, int E, int nWG, int nFC) {
    extern __shared__ float sm[];
    if ((int)blockIdx.x < nWG) wgemm_dev(sm, evec, Wfc1, 0, g_wb0, E, blockIdx.x, 1);
    else fctp1_dev(sm, attr, x, W0, W1, L0, L1, N, blockIdx.x - nWG, nFC);
}

__global__ void __launch_bounds__(256, 3)
k_fusedC(const float* __restrict__ attr, const float* __restrict__ evec,
         const float* __restrict__ W20, const float* __restrict__ W21,
         const float* __restrict__ W0b, const float* __restrict__ W1b,
         const float* __restrict__ L0b, const float* __restrict__ L1b,
         const float* __restrict__ Wfc1,
         int N, int E, int nWG, int nFC) {
    extern __shared__ float sm[];
    if ((int)blockIdx.x < nWG) {
        wgemm_dev(sm, evec, Wfc1, 8192, g_wb1, E, blockIdx.x, 0);
    } else {
        int rb = blockIdx.x - nWG;
        fctp2_dev(sm, attr, W20, W21, N, rb, nFC);
        __syncthreads();
        fctp1_dev(sm, attr, nullptr, W0b, W1b, L0b, L1b, N, rb, nFC);
    }
}

__global__ void __launch_bounds__(256, 3)
k_fctp2(const float* __restrict__ attr,
        const float* __restrict__ W20, const float* __restrict__ W21, int N) {
    extern __shared__ float sm[];
    fctp2_dev(sm, attr, W20, W21, N, blockIdx.x, gridDim.x);
}

// ---------------- readout + pooling (+ restores g_deg=0) ------
__global__ void k_zero_out(float* out) { out[threadIdx.x] = 0.0f; }

__global__ void k_read(const float* __restrict__ attr, const int* __restrict__ batch,
                       const float* __restrict__ Wread, float* __restrict__ out,
                       int N, float poolscale) {
    __shared__ float shW[2048];
    __shared__ float pool[128];
    for (int i = blockIdx.x * blockDim.x + threadIdx.x; i < N;
         i += gridDim.x * blockDim.x)
        g_deg[i] = 0;
    for (int i = threadIdx.x; i < 2048; i += blockDim.x) shW[i] = Wread[i];
    if (threadIdx.x < 128) pool[threadIdx.x] = 0.0f;
    __syncthreads();
    int lane = threadIdx.x & 31;
    int wid  = blockIdx.x * (blockDim.x >> 5) + (threadIdx.x >> 5);
    int wstr = gridDim.x * (blockDim.x >> 5);
    int w = lane & 15;
    for (int n = wid; n < N; n += wstr) {
        float sl = g_s[n*32 + lane];
        float at[4] = {attr[n*4+0], attr[n*4+1], attr[n*4+2], attr[n*4+3]};
        float acc = 0.f;
        for (int u = 0; u < 32; u++) {
            float su = __shfl_sync(0xffffffffu, sl, u);
            int base = u*64 + w;
#pragma unroll
            for (int a = 0; a < 4; a++) acc += su*at[a]*shW[base + a*16];
        }
        if (lane < 16) {
            int g = batch[n];
            atomicAdd(&pool[g*16 + w], acc * NORM128 * poolscale);
        }
    }
    __syncthreads();
    if (threadIdx.x < 128) atomicAdd(&out[threadIdx.x], pool[threadIdx.x]);
}

// ---------------- launcher ----------------
extern "C" void kernel_launch(void* const* d_in, const int* in_sizes, int n_in,
                              void* d_out, int out_size) {
    const float* x    = (const float*)d_in[0];
    const float* attr = (const float*)d_in[1];
    const float* evec = (const float*)d_in[2];
    const int*   batch= (const int*)  d_in[3];
    const int*   esrc = (const int*)  d_in[4];
    const int*   edst = (const int*)  d_in[5];
    const float* Wsc0 = (const float*)d_in[6];
    const float* Wsc1 = (const float*)d_in[7];
    const float* Wl10 = (const float*)d_in[8];
    const float* Wl11 = (const float*)d_in[9];
    const float* Wfc1 = (const float*)d_in[10];
    const float* Wfc2 = (const float*)d_in[11];
    const float* Wl20 = (const float*)d_in[12];
    const float* Wl21 = (const float*)d_in[13];
    const float* Wread= (const float*)d_in[14];
    int N = in_sizes[0] / 128;
    int E = in_sizes[4];

    cudaFuncSetAttribute(k_fusedA, cudaFuncAttributeMaxDynamicSharedMemorySize, FUSED_SMEM);
    cudaFuncSetAttribute(k_fusedC, cudaFuncAttributeMaxDynamicSharedMemorySize, FUSED_SMEM);
    cudaFuncSetAttribute(k_fctp2,  cudaFuncAttributeMaxDynamicSharedMemorySize, FUSED_SMEM);

    int nWG = (E + WG_TE - 1) / WG_TE;
    int nFC = 444;
    int nGB = (N + 1) / 2;

    // preconvert W2 + CSR build
    k_cvt<<<64, 256>>>(Wfc2);
    k_hist<<<(E + 255) / 256, 256>>>(edst, E);
    k_scan<<<1, SCAN_T>>>(N);
    k_fill<<<(E + 255) / 256, 256>>>(esrc, edst, E);

    // layer 0 (+ hidden wgemm(L1) and fctp1(L1))
    k_fusedA<<<nWG + nFC, 256, FUSED_SMEM>>>(attr, x, evec,
                                             Wsc0, Wsc1, Wl10, Wl11,
                                             Wfc1, N, E, nWG, nFC);
    k_gather<0><<<nGB, 256>>>(N);
    k_fusedC<<<nWG + nFC, 256, FUSED_SMEM>>>(attr, evec, Wl20, Wl21,
                                             Wsc0 + 4096, Wsc1 + 4096,
                                             Wl10 + 4096, Wl11 + 4096,
                                             Wfc1 + 640, N, E, nWG, nFC);
    // layer 1 (wgemm + fctp1 already done)
    k_gather<1><<<nGB, 256>>>(N);
    k_fctp2<<<444, 256, FUSED_SMEM>>>(attr, Wl20 + 8192, Wl21 + 8192, N);

    k_zero_out<<<1, 128>>>((float*)d_out);
    float poolscale = 1.0f / sqrtf((float)N / 8.0f);
    k_read<<<592, 128>>>(attr, batch, Wread, (float*)d_out, N, poolscale);
}

// round 16
// speedup vs baseline: 1.4963x; 1.4963x over previous
#include <cuda_runtime.h>
#include <cuda_bf16.h>
#include <math.h>

#define MAXN 10000
#define MAXE 320000

// ---------------- scratch (device globals; no runtime alloc) ----------------
__device__ float g_s  [MAXN*32];
__device__ float g_v  [MAXN*96];    // (N,3,32)
__device__ float g_scs[MAXN*32];
__device__ float g_scv[MAXN*96];
__device__ float g_xs [MAXN*32];
__device__ float g_xv [MAXN*96];
__device__ float g_aggs[MAXN*64];
__device__ float g_aggv[MAXN*192];
// CSR (by dst) + permuted edge data
__device__ int   g_deg   [MAXN];     // zero-initialized; restored to 0 by k_read
__device__ int   g_cursor[MAXN];
__device__ int   g_rowstart[MAXN+1];
__device__ int   g_srcP  [MAXE];
__device__ int   g_invP  [MAXE];     // permuted slot -> original edge id
__device__ float g_YP    [MAXE*3];
// per-edge radial weights, bf16, double-buffered per layer
__device__ __nv_bfloat16 g_wb0[MAXE*128];
__device__ __nv_bfloat16 g_wb1[MAXE*128];
// Wfc2 preconverted to bf16 (both layers)
__device__ __nv_bfloat16 g_w2b[16384];

// ---------------- constants ----------------
#define SQRT3F   1.7320508075688772f
#define ISQRT3F  0.5773502691896258f
#define INV_NB   0.17677669529663687f
#define NORM128  0.08838834764831845f
#define NORM256  0.0625f
#define INVS10   0.3162277660168379f
#define C_S      0.3826834323650898f
#define C_X      0.9238795325112867f
#define PI_F     3.14159265358979f
#define WG_TE    128
#define FUSED_SMEM 65536
#define HB_STR   72     // shHb row stride in bf16 (144 B)
#define W2_STR   136    // shW2b row stride in bf16 (272 B)

typedef unsigned long long ull;

// ---------------- packed f32x2 helpers ----------------
__device__ __forceinline__ ull pack2(float lo, float hi) {
    ull r;
    asm("mov.b64 %0, {%1, %2};" : "=l"(r) : "f"(lo), "f"(hi));
    return r;
}
__device__ __forceinline__ void ffma2(ull& acc, ull a, ull b) {
    asm("fma.rn.f32x2 %0, %1, %2, %0;" : "+l"(acc) : "l"(a), "l"(b));
}
__device__ __forceinline__ ull mul2r(ull a, ull b) {
    ull r;
    asm("mul.rn.f32x2 %0, %1, %2;" : "=l"(r) : "l"(a), "l"(b));
    return r;
}
__device__ __forceinline__ float2 unpack2(ull v) {
    float2 f;
    asm("mov.b64 {%0, %1}, %2;" : "=f"(f.x), "=f"(f.y) : "l"(v));
    return f;
}
__device__ __forceinline__ unsigned int bf16x2_of(float a, float b) {
    unsigned int r;
    asm("cvt.rn.bf16x2.f32 %0, %1, %2;" : "=r"(r) : "f"(b), "f"(a));
    return r;
}
__device__ __forceinline__ unsigned int sptr(const void* p) {
    return (unsigned int)__cvta_generic_to_shared(p);
}
__device__ __forceinline__ void mma16816(float* d, const unsigned* a,
                                         unsigned b0, unsigned b1) {
    asm volatile(
        "mma.sync.aligned.m16n8k16.row.col.f32.bf16.bf16.f32 "
        "{%0,%1,%2,%3}, {%4,%5,%6,%7}, {%8,%9}, {%0,%1,%2,%3};"
        : "+f"(d[0]), "+f"(d[1]), "+f"(d[2]), "+f"(d[3])
        : "r"(a[0]), "r"(a[1]), "r"(a[2]), "r"(a[3]), "r"(b0), "r"(b1));
}

// ---------------- tiny preconversion ----------------
__global__ void k_cvt(const float* __restrict__ Wfc2) {
    int i = blockIdx.x * blockDim.x + threadIdx.x;
    if (i < 16384) g_w2b[i] = __float2bfloat16(Wfc2[i]);
}

// ---------------- CSR build ----------------
__global__ void k_hist(const int* __restrict__ edst, int E) {
    int e = blockIdx.x * blockDim.x + threadIdx.x;
    if (e < E) atomicAdd(&g_deg[edst[e]], 1);
}
#define SCAN_T 1024
__global__ void k_scan(int N) {
    __shared__ int sums[SCAN_T];
    int t = threadIdx.x;
    int IT = (N + SCAN_T - 1) / SCAN_T;
    int lo = t * IT, hi = lo + IT; if (hi > N) hi = N; if (lo > N) lo = N;
    int s = 0;
    for (int i = lo; i < hi; i++) s += g_deg[i];
    sums[t] = s;
    __syncthreads();
    for (int off = 1; off < SCAN_T; off <<= 1) {
        int v = (t >= off) ? sums[t - off] : 0;
        __syncthreads();
        sums[t] += v;
        __syncthreads();
    }
    int run = (t == 0) ? 0 : sums[t - 1];
    for (int i = lo; i < hi; i++) {
        g_rowstart[i] = run;
        g_cursor[i]   = run;
        run += g_deg[i];
    }
    if (hi == N) g_rowstart[N] = run;
}
__global__ void k_fill(const int* __restrict__ esrc, const int* __restrict__ edst, int E) {
    int e = blockIdx.x * blockDim.x + threadIdx.x;
    if (e >= E) return;
    int pos = atomicAdd(&g_cursor[edst[e]], 1);
    g_srcP[pos] = esrc[e];
    g_invP[pos] = e;
}

// ================= device bodies ======================

// --- fctp1: packed f32x2, interleaved weight pairs (64 KB smem) ---
__device__ void fctp1_dev(float* sm, const float* __restrict__ attr,
                          const float* __restrict__ xin,
                          const float* __restrict__ W0, const float* __restrict__ W1,
                          const float* __restrict__ L0, const float* __restrict__ L1,
                          int N, int relBid, int nBlocks) {
    float2* sW02 = (float2*)sm;
    float2* sW12 = (float2*)(sm + 8192);
    for (int i = threadIdx.x; i < 4096; i += 256) {
        sW02[i] = make_float2(W0[i], L0[i]);
        sW12[i] = make_float2(W1[i], L1[i]);
    }
    __syncthreads();
    const ull* w02 = (const ull*)sW02;
    const ull* w12 = (const ull*)sW12;
    int lane = threadIdx.x & 31;
    int wid  = relBid * 8 + (threadIdx.x >> 5);
    int wstr = nBlocks * 8;
    for (int n = wid; n < N; n += wstr) {
        float sl, v0, v1, v2;
        if (xin) {
            sl = xin[n*128 + lane];
            v0 = xin[n*128 + 32 + lane*3 + 0];
            v1 = xin[n*128 + 32 + lane*3 + 1];
            v2 = xin[n*128 + 32 + lane*3 + 2];
            g_s[n*32+lane]      = sl;
            g_v[n*96+lane]      = v0;
            g_v[n*96+32+lane]   = v1;
            g_v[n*96+64+lane]   = v2;
        } else {
            sl = g_s[n*32 + lane];
            v0 = g_v[n*96 + lane];
            v1 = g_v[n*96 + 32 + lane];
            v2 = g_v[n*96 + 64 + lane];
        }
        ull atp[4];
#pragma unroll
        for (int a = 0; a < 4; a++) { float av = attr[n*4+a]; atp[a] = pack2(av, av); }
        ull accS = 0ull, accV0 = 0ull, accV1 = 0ull, accV2 = 0ull;
        for (int u = 0; u < 32; u++) {
            float su  = __shfl_sync(0xffffffffu, sl, u);
            float vu0 = __shfl_sync(0xffffffffu, v0, u);
            float vu1 = __shfl_sync(0xffffffffu, v1, u);
            float vu2 = __shfl_sync(0xffffffffu, v2, u);
            ull sup = pack2(su, su);
            ull v0p = pack2(vu0, vu0);
            ull v1p = pack2(vu1, vu1);
            ull v2p = pack2(vu2, vu2);
            int base = u*128 + lane;
#pragma unroll
            for (int a = 0; a < 4; a++) {
                int wi = base + a*32;
                ull wa = w02[wi];
                ull wb = w12[wi];
                ffma2(accS,  mul2r(sup, atp[a]), wa);
                ffma2(accV0, mul2r(v0p, atp[a]), wb);
                ffma2(accV1, mul2r(v1p, atp[a]), wb);
                ffma2(accV2, mul2r(v2p, atp[a]), wb);
            }
        }
        float2 fS  = unpack2(accS);
        float2 fV0 = unpack2(accV0);
        float2 fV1 = unpack2(accV1);
        float2 fV2 = unpack2(accV2);
        g_scs[n*32+lane] = fS.x*NORM128;
        g_xs [n*32+lane] = fS.y*NORM128;
        g_scv[n*96+lane]      = fV0.x*NORM128;
        g_scv[n*96+32+lane]   = fV1.x*NORM128;
        g_scv[n*96+64+lane]   = fV2.x*NORM128;
        g_xv [n*96+lane]      = fV0.y*NORM128;
        g_xv [n*96+32+lane]   = fV1.y*NORM128;
        g_xv [n*96+64+lane]   = fV2.y*NORM128;
    }
}

// --- wgemm: 128-edge tile; h,W2 bf16 smem; h@W2 on tensor pipe ---
__device__ void wgemm_dev(float* sm, const float* __restrict__ evec,
                          const float* __restrict__ Wfc1, int w2off,
                          __nv_bfloat16* __restrict__ wout, int E, int bid,
                          int writeY) {
    float* shW1  = sm;                              // 640 f
    float* shEmb = sm + 640;                        // 1280 f
    __nv_bfloat16* shW2b = (__nv_bfloat16*)(sm + 1920);         // 64 x 136 bf16
    __nv_bfloat16* shHb  = (__nv_bfloat16*)(sm + 1920 + 4352);  // 128 x 72 bf16
    int tid = threadIdx.x;
    int eg0 = bid * WG_TE;
    int nE = E - eg0; if (nE > WG_TE) nE = WG_TE;

    for (int i = tid; i < 640; i += 256) shW1[i] = Wfc1[i];
    // W2 staged from preconverted bf16 with 16B copies
    {
        const uint4* src = (const uint4*)(g_w2b + w2off);   // 1024 uint4
        for (int i = tid; i < 1024; i += 256) {
            int k = i >> 4, c = i & 15;
            *(uint4*)&shW2b[k*W2_STR + c*8] = src[i];
        }
    }
    if (tid < WG_TE) {
        if (tid < nE) {
            int p = eg0 + tid;
            int e = g_invP[p];
            float vx = evec[e*3+0], vy = evec[e*3+1], vz = evec[e*3+2];
            float len = sqrtf(vx*vx + vy*vy + vz*vz);
            if (writeY) {
                float inv = 1.0f / (len + 1e-9f);
                g_YP[p*3+0] = SQRT3F * vx * inv;
                g_YP[p*3+1] = SQRT3F * vy * inv;
                g_YP[p*3+2] = SQRT3F * vz * inv;
            }
            float uu = 0.5f*len - 2.0f;
            float cut;
            if (uu > 0.0f)       cut = 0.0f;
            else if (uu < -1.0f) cut = 1.0f;
            else                 cut = (1.0f - __cosf(PI_F * uu)) * 0.5f;
#pragma unroll
            for (int b = 0; b < 10; b++) {
                float c = (4.0f/9.0f) * (float)b;
                float d = (len - c) * 2.5f;
                shEmb[tid*10+b] = __expf(-d*d) * cut;
            }
        } else {
#pragma unroll
            for (int b = 0; b < 10; b++) shEmb[tid*10+b] = 0.f;
        }
    }
    __syncthreads();

    // phase 1: h = silu(emb @ W1 / sqrt(10)) -> bf16 smem
    for (int idx = tid; idx < WG_TE*64; idx += 256) {
        int e = idx >> 6, k = idx & 63;
        float acc = 0.f;
#pragma unroll
        for (int b = 0; b < 10; b++) acc += shEmb[e*10+b] * shW1[b*64+k];
        acc *= INVS10;
        shHb[e*HB_STR + k] = __float2bfloat16(acc / (1.0f + __expf(-acc)));
    }
    __syncthreads();

    // phase 2: tensor-core GEMM. warp tile = 32 edges x 64 cols.
    int lane = tid & 31;
    int warp = tid >> 5;
    int eb = (warp & 3) * 32;
    int nb = (warp >> 2) * 64;

    unsigned a[2][4][4];
    {
        int r  = lane & 15;
        int cA = (lane >> 4) << 3;
#pragma unroll
        for (int mt = 0; mt < 2; mt++)
#pragma unroll
            for (int kc = 0; kc < 4; kc++) {
                unsigned ad = sptr(&shHb[(eb + mt*16 + r)*HB_STR + kc*16 + cA]);
                asm volatile(
                    "ldmatrix.sync.aligned.m8n8.x4.shared.b16 {%0,%1,%2,%3}, [%4];"
                    : "=r"(a[mt][kc][0]), "=r"(a[mt][kc][1]),
                      "=r"(a[mt][kc][2]), "=r"(a[mt][kc][3])
                    : "r"(ad));
            }
    }

    int row  = lane >> 2;
    int colp = (lane & 3) * 2;
#pragma unroll
    for (int nt = 0; nt < 8; nt++) {
        float acc0[4] = {0.f, 0.f, 0.f, 0.f};
        float acc1[4] = {0.f, 0.f, 0.f, 0.f};
#pragma unroll
        for (int kc = 0; kc < 4; kc++) {
            int rk = lane & 15;
            unsigned bd = sptr(&shW2b[(kc*16 + rk)*W2_STR + nb + nt*8]);
            unsigned b0, b1;
            asm volatile(
                "ldmatrix.sync.aligned.m8n8.x2.trans.shared.b16 {%0,%1}, [%2];"
                : "=r"(b0), "=r"(b1) : "r"(bd));
            mma16816(acc0, a[0][kc], b0, b1);
            mma16816(acc1, a[1][kc], b0, b1);
        }
        int col = nb + nt*8 + colp;
        int geA = eg0 + eb + row;
        int geB = geA + 8;
        int geC = geA + 16;
        int geD = geA + 24;
        if (geA < E)
            *(unsigned*)&wout[(size_t)geA*128 + col] = bf16x2_of(acc0[0]*0.125f, acc0[1]*0.125f);
        if (geB < E)
            *(unsigned*)&wout[(size_t)geB*128 + col] = bf16x2_of(acc0[2]*0.125f, acc0[3]*0.125f);
        if (geC < E)
            *(unsigned*)&wout[(size_t)geC*128 + col] = bf16x2_of(acc1[0]*0.125f, acc1[1]*0.125f);
        if (geD < E)
            *(unsigned*)&wout[(size_t)geD*128 + col] = bf16x2_of(acc1[2]*0.125f, acc1[3]*0.125f);
    }
}

// --- fctp2: packed f32x2 + gated state update (64 KB smem) ---
__device__ void fctp2_dev(float* sm, const float* __restrict__ attr,
                          const float* __restrict__ W20, const float* __restrict__ W21,
                          int N, int relBid, int nBlocks) {
    float2* sWp = (float2*)sm;
    for (int i = threadIdx.x; i < 8192; i += 256)
        sWp[i] = make_float2(W20[i], W21[i]);
    __syncthreads();
    const ull* wPair = (const ull*)sWp;
    int lane = threadIdx.x & 31;
    int wid  = relBid * 8 + (threadIdx.x >> 5);
    int wstr = nBlocks * 8;
    for (int n = wid; n < N; n += wstr) {
        float sa  = g_aggs[n*64 + lane],        sb  = g_aggs[n*64 + 32 + lane];
        float va0 = g_aggv[n*192 + lane],       vb0 = g_aggv[n*192 + 32 + lane];
        float va1 = g_aggv[n*192 + 64 + lane],  vb1 = g_aggv[n*192 + 96 + lane];
        float va2 = g_aggv[n*192 + 128 + lane], vb2 = g_aggv[n*192 + 160 + lane];
        ull atp[4];
#pragma unroll
        for (int a = 0; a < 4; a++) { float av = attr[n*4+a]; atp[a] = pack2(av, av); }
        ull accA = 0ull;   // {os, ov2}
        ull accB = 0ull;   // {ov0, ov1}
#pragma unroll 1
        for (int half = 0; half < 2; half++) {
            float ss  = half ? sb  : sa;
            float vv0 = half ? vb0 : va0;
            float vv1 = half ? vb1 : va1;
            float vv2 = half ? vb2 : va2;
            int uoff = half ? 32 : 0;
            for (int u = 0; u < 32; u++) {
                float su = __shfl_sync(0xffffffffu, ss,  u);
                float w0 = __shfl_sync(0xffffffffu, vv0, u);
                float w1 = __shfl_sync(0xffffffffu, vv1, u);
                float w2 = __shfl_sync(0xffffffffu, vv2, u);
                ull pA = pack2(su, w2);
                ull pB = pack2(w0, w1);
                int base = (u + uoff)*128 + lane;
#pragma unroll
                for (int a = 0; a < 4; a++) {
                    int wi = base + a*32;
                    ull wp = wPair[wi];
                    float2 wf = unpack2(wp);
                    ull wdup = pack2(wf.y, wf.y);
                    ffma2(accA, mul2r(pA, atp[a]), wp);
                    ffma2(accB, mul2r(pB, atp[a]), wdup);
                }
            }
        }
        float2 fA = unpack2(accA);
        float2 fB = unpack2(accB);
        float os  = fA.x*NORM256, ov2 = fA.y*NORM256;
        float ov0 = fB.x*NORM256, ov1 = fB.y*NORM256;
        float sn  = C_S * g_scs[n*32+lane] + C_X * os;
        float sig = 1.0f / (1.0f + __expf(-sn));
        g_s[n*32+lane] += sn * sig;
        float vn0 = C_S * g_scv[n*96+lane]      + C_X * ov0;
        float vn1 = C_S * g_scv[n*96+32+lane]   + C_X * ov1;
        float vn2 = C_S * g_scv[n*96+64+lane]   + C_X * ov2;
        g_v[n*96+lane]      += vn0 * sig;
        g_v[n*96+32+lane]   += vn1 * sig;
        g_v[n*96+64+lane]   += vn2 * sig;
    }
}

// ================= gather: dual independent edge streams (fp32 features) =====
template<int BUF>
__global__ void __launch_bounds__(256)
k_gather(int N) {
    const __nv_bfloat16* __restrict__ win = BUF ? g_wb1 : g_wb0;
    int tid = threadIdx.x;
    int n = blockIdx.x*2 + (tid >> 7);
    if (n >= N) return;
    int sub = tid & 127;
    int k = sub >> 5, u = sub & 31;
    int t0 = g_rowstart[n], t1 = g_rowstart[n+1];
    int len  = t1 - t0;
    int hlen = (len + 1) >> 1;
    int tB0  = t0 + hlen;
    float a0 = 0.f, a1 = 0.f, a2 = 0.f;
    float b0 = 0.f, b1 = 0.f, b2 = 0.f;

    if (k == 0) {
        for (int i = 0; i < hlen; i++) {
            int eA = t0 + i, eB = tB0 + i;
            bool vB = (eB < t1);
            int sA = g_srcP[eA];
            int sB = vB ? g_srcP[eB] : 0;
            float wA = __bfloat162float(win[(size_t)eA*128 + u]);
            float wB = vB ? __bfloat162float(win[(size_t)eB*128 + u]) : 0.f;
            a0 += wA * g_xs[sA*32 + u];
            b0 += wB * g_xs[sB*32 + u];
        }
        g_aggs[n*64 + u] = (a0 + b0) * INV_NB;
    } else if (k == 1) {
        for (int i = 0; i < hlen; i++) {
            int eA = t0 + i, eB = tB0 + i;
            bool vB = (eB < t1);
            int sA = g_srcP[eA];
            int sB = vB ? g_srcP[eB] : 0;
            float wA = __bfloat162float(win[(size_t)eA*128 + 32 + u]);
            float wB = vB ? __bfloat162float(win[(size_t)eB*128 + 32 + u]) : 0.f;
            float dA = g_YP[eA*3+0]*g_xv[sA*96+u] + g_YP[eA*3+1]*g_xv[sA*96+32+u]
                     + g_YP[eA*3+2]*g_xv[sA*96+64+u];
            float dB = g_YP[eB < t1 ? eB*3+0 : 0]*g_xv[sB*96+u]
                     + g_YP[eB < t1 ? eB*3+1 : 0]*g_xv[sB*96+32+u]
                     + g_YP[eB < t1 ? eB*3+2 : 0]*g_xv[sB*96+64+u];
            a0 += wA * dA;
            b0 += wB * dB;
        }
        g_aggs[n*64 + 32 + u] = (a0 + b0) * ISQRT3F * INV_NB;
    } else if (k == 2) {
        for (int i = 0; i < hlen; i++) {
            int eA = t0 + i, eB = tB0 + i;
            bool vB = (eB < t1);
            int sA = g_srcP[eA];
            int sB = vB ? g_srcP[eB] : 0;
            float wA = __bfloat162float(win[(size_t)eA*128 + 64 + u]);
            float wB = vB ? __bfloat162float(win[(size_t)eB*128 + 64 + u]) : 0.f;
            float mA = wA * g_xs[sA*32 + u];
            float mB = wB * g_xs[sB*32 + u];
            a0 += mA * g_YP[eA*3+0];
            a1 += mA * g_YP[eA*3+1];
            a2 += mA * g_YP[eA*3+2];
            int eBs = vB ? eB : eA;
            b0 += mB * g_YP[eBs*3+0];
            b1 += mB * g_YP[eBs*3+1];
            b2 += mB * g_YP[eBs*3+2];
        }
        g_aggv[n*192 +       u] = (a0 + b0) * INV_NB;
        g_aggv[n*192 +  64 + u] = (a1 + b1) * INV_NB;
        g_aggv[n*192 + 128 + u] = (a2 + b2) * INV_NB;
    } else {
        for (int i = 0; i < hlen; i++) {
            int eA = t0 + i, eB = tB0 + i;
            bool vB = (eB < t1);
            int sA = g_srcP[eA];
            int sB = vB ? g_srcP[eB] : 0;
            float wA = __bfloat162float(win[(size_t)eA*128 + 96 + u]);
            float wB = vB ? __bfloat162float(win[(size_t)eB*128 + 96 + u]) : 0.f;
            a0 += wA * g_xv[sA*96 + u];
            a1 += wA * g_xv[sA*96 + 32 + u];
            a2 += wA * g_xv[sA*96 + 64 + u];
            b0 += wB * g_xv[sB*96 + u];
            b1 += wB * g_xv[sB*96 + 32 + u];
            b2 += wB * g_xv[sB*96 + 64 + u];
        }
        g_aggv[n*192 +  32 + u] = (a0 + b0) * INV_NB;
        g_aggv[n*192 +  96 + u] = (a1 + b1) * INV_NB;
        g_aggv[n*192 + 160 + u] = (a2 + b2) * INV_NB;
    }
}

// ================= launches ======================

__global__ void __launch_bounds__(256, 3)
k_fusedA(const float* __restrict__ attr, const float* __restrict__ x,
         const float* __restrict__ evec,
         const float* __restrict__ W0, const float* __restrict__ W1,
         const float* __restrict__ L0, const float* __restrict__ L1,
         const float* __restrict__ Wfc1,
         int N, int E, int nWG, int nFC) {
    extern __shared__ float sm[];
    if ((int)blockIdx.x < nWG) wgemm_dev(sm, evec, Wfc1, 0, g_wb0, E, blockIdx.x, 1);
    else fctp1_dev(sm, attr, x, W0, W1, L0, L1, N, blockIdx.x - nWG, nFC);
}

__global__ void __launch_bounds__(256, 3)
k_fusedC(const float* __restrict__ attr, const float* __restrict__ evec,
         const float* __restrict__ W20, const float* __restrict__ W21,
         const float* __restrict__ W0b, const float* __restrict__ W1b,
         const float* __restrict__ L0b, const float* __restrict__ L1b,
         const float* __restrict__ Wfc1,
         int N, int E, int nWG, int nFC) {
    extern __shared__ float sm[];
    if ((int)blockIdx.x < nWG) {
        wgemm_dev(sm, evec, Wfc1, 8192, g_wb1, E, blockIdx.x, 0);
    } else {
        int rb = blockIdx.x - nWG;
        fctp2_dev(sm, attr, W20, W21, N, rb, nFC);
        __syncthreads();
        fctp1_dev(sm, attr, nullptr, W0b, W1b, L0b, L1b, N, rb, nFC);
    }
}

__global__ void __launch_bounds__(256, 3)
k_fctp2(const float* __restrict__ attr,
        const float* __restrict__ W20, const float* __restrict__ W21, int N) {
    extern __shared__ float sm[];
    fctp2_dev(sm, attr, W20, W21, N, blockIdx.x, gridDim.x);
}

// ---------------- readout + pooling (+ restores g_deg=0 for next call) ------
__global__ void k_zero_out(float* out) { out[threadIdx.x] = 0.0f; }

__global__ void k_read(const float* __restrict__ attr, const int* __restrict__ batch,
                       const float* __restrict__ Wread, float* __restrict__ out,
                       int N, float poolscale) {
    __shared__ float shW[2048];
    __shared__ float pool[128];
    for (int i = blockIdx.x * blockDim.x + threadIdx.x; i < N;
         i += gridDim.x * blockDim.x)
        g_deg[i] = 0;
    for (int i = threadIdx.x; i < 2048; i += blockDim.x) shW[i] = Wread[i];
    if (threadIdx.x < 128) pool[threadIdx.x] = 0.0f;
    __syncthreads();
    int lane = threadIdx.x & 31;
    int wid  = blockIdx.x * (blockDim.x >> 5) + (threadIdx.x >> 5);
    int wstr = gridDim.x * (blockDim.x >> 5);
    int w = lane & 15;
    for (int n = wid; n < N; n += wstr) {
        float sl = g_s[n*32 + lane];
        float at[4] = {attr[n*4+0], attr[n*4+1], attr[n*4+2], attr[n*4+3]};
        float acc = 0.f;
        for (int u = 0; u < 32; u++) {
            float su = __shfl_sync(0xffffffffu, sl, u);
            int base = u*64 + w;
#pragma unroll
            for (int a = 0; a < 4; a++) acc += su*at[a]*shW[base + a*16];
        }
        if (lane < 16) {
            int g = batch[n];
            atomicAdd(&pool[g*16 + w], acc * NORM128 * poolscale);
        }
    }
    __syncthreads();
    if (threadIdx.x < 128) atomicAdd(&out[threadIdx.x], pool[threadIdx.x]);
}

// ---------------- launcher ----------------
extern "C" void kernel_launch(void* const* d_in, const int* in_sizes, int n_in,
                              void* d_out, int out_size) {
    const float* x    = (const float*)d_in[0];
    const float* attr = (const float*)d_in[1];
    const float* evec = (const float*)d_in[2];
    const int*   batch= (const int*)  d_in[3];
    const int*   esrc = (const int*)  d_in[4];
    const int*   edst = (const int*)  d_in[5];
    const float* Wsc0 = (const float*)d_in[6];
    const float* Wsc1 = (const float*)d_in[7];
    const float* Wl10 = (const float*)d_in[8];
    const float* Wl11 = (const float*)d_in[9];
    const float* Wfc1 = (const float*)d_in[10];
    const float* Wfc2 = (const float*)d_in[11];
    const float* Wl20 = (const float*)d_in[12];
    const float* Wl21 = (const float*)d_in[13];
    const float* Wread= (const float*)d_in[14];
    int N = in_sizes[0] / 128;
    int E = in_sizes[4];

    cudaFuncSetAttribute(k_fusedA, cudaFuncAttributeMaxDynamicSharedMemorySize, FUSED_SMEM);
    cudaFuncSetAttribute(k_fusedC, cudaFuncAttributeMaxDynamicSharedMemorySize, FUSED_SMEM);
    cudaFuncSetAttribute(k_fctp2,  cudaFuncAttributeMaxDynamicSharedMemorySize, FUSED_SMEM);

    int nWG = (E + WG_TE - 1) / WG_TE;
    int nFC = 444;
    int nGB = (N + 1) / 2;

    // preconvert W2 + CSR build (g_deg zeroed by previous call's k_read / static init)
    k_cvt<<<64, 256>>>(Wfc2);
    k_hist<<<(E + 255) / 256, 256>>>(edst, E);
    k_scan<<<1, SCAN_T>>>(N);
    k_fill<<<(E + 255) / 256, 256>>>(esrc, edst, E);

    // layer 0 (+ hidden wgemm(L1) and fctp1(L1))
    k_fusedA<<<nWG + nFC, 256, FUSED_SMEM>>>(attr, x, evec,
                                             Wsc0, Wsc1, Wl10, Wl11,
                                             Wfc1, N, E, nWG, nFC);
    k_gather<0><<<nGB, 256>>>(N);
    k_fusedC<<<nWG + nFC, 256, FUSED_SMEM>>>(attr, evec, Wl20, Wl21,
                                             Wsc0 + 4096, Wsc1 + 4096,
                                             Wl10 + 4096, Wl11 + 4096,
                                             Wfc1 + 640, N, E, nWG, nFC);
    // layer 1 (wgemm + fctp1 already done)
    k_gather<1><<<nGB, 256>>>(N);
    k_fctp2<<<444, 256, FUSED_SMEM>>>(attr, Wl20 + 8192, Wl21 + 8192, N);

    k_zero_out<<<1, 128>>>((float*)d_out);
    float poolscale = 1.0f / sqrtf((float)N / 8.0f);
    k_read<<<592, 128>>>(attr, batch, Wread, (float*)d_out, N, poolscale);
}

// round 17
// speedup vs baseline: 1.5275x; 1.0208x over previous
#include <cuda_runtime.h>
#include <cuda_bf16.h>
#include <math.h>

#define MAXN 10000
#define MAXE 320000

// ---------------- scratch (device globals; no runtime alloc) ----------------
__device__ float g_s  [MAXN*32];
__device__ float g_v  [MAXN*96];    // (N,3,32)
__device__ float g_scs[MAXN*32];
__device__ float g_scv[MAXN*96];
__device__ float g_xs [MAXN*32];
__device__ float g_xv [MAXN*96];
__device__ float g_aggs[MAXN*64];
__device__ float g_aggv[MAXN*192];
// CSR (by dst) + permuted edge data
__device__ int   g_deg   [MAXN];     // zero-initialized; restored by k_fctp2read
__device__ int   g_cursor[MAXN];
__device__ int   g_rowstart[MAXN+1];
__device__ int   g_srcP  [MAXE];
__device__ int   g_invP  [MAXE];
__device__ float g_YP    [MAXE*3];
// per-edge radial weights, bf16, double-buffered per layer
__device__ __nv_bfloat16 g_wb0[MAXE*128];
__device__ __nv_bfloat16 g_wb1[MAXE*128];
// Wfc2 preconverted to bf16 (both layers)
__device__ __nv_bfloat16 g_w2b[16384];

// ---------------- constants ----------------
#define SQRT3F   1.7320508075688772f
#define ISQRT3F  0.5773502691896258f
#define INV_NB   0.17677669529663687f
#define NORM128  0.08838834764831845f
#define NORM256  0.0625f
#define INVS10   0.3162277660168379f
#define C_S      0.3826834323650898f
#define C_X      0.9238795325112867f
#define PI_F     3.14159265358979f
#define WG_TE    128
#define FUSED_SMEM 65536
#define READ_SMEM  74240   // 64KB weights + 8KB Wread + 512B pool
#define HB_STR   72
#define W2_STR   136

typedef unsigned long long ull;

// ---------------- packed f32x2 helpers ----------------
__device__ __forceinline__ ull pack2(float lo, float hi) {
    ull r;
    asm("mov.b64 %0, {%1, %2};" : "=l"(r) : "f"(lo), "f"(hi));
    return r;
}
__device__ __forceinline__ void ffma2(ull& acc, ull a, ull b) {
    asm("fma.rn.f32x2 %0, %1, %2, %0;" : "+l"(acc) : "l"(a), "l"(b));
}
__device__ __forceinline__ ull mul2r(ull a, ull b) {
    ull r;
    asm("mul.rn.f32x2 %0, %1, %2;" : "=l"(r) : "l"(a), "l"(b));
    return r;
}
__device__ __forceinline__ float2 unpack2(ull v) {
    float2 f;
    asm("mov.b64 {%0, %1}, %2;" : "=f"(f.x), "=f"(f.y) : "l"(v));
    return f;
}
__device__ __forceinline__ unsigned int bf16x2_of(float a, float b) {
    unsigned int r;
    asm("cvt.rn.bf16x2.f32 %0, %1, %2;" : "=r"(r) : "f"(b), "f"(a));
    return r;
}
__device__ __forceinline__ unsigned int sptr(const void* p) {
    return (unsigned int)__cvta_generic_to_shared(p);
}
__device__ __forceinline__ void mma16816(float* d, const unsigned* a,
                                         unsigned b0, unsigned b1) {
    asm volatile(
        "mma.sync.aligned.m16n8k16.row.col.f32.bf16.bf16.f32 "
        "{%0,%1,%2,%3}, {%4,%5,%6,%7}, {%8,%9}, {%0,%1,%2,%3};"
        : "+f"(d[0]), "+f"(d[1]), "+f"(d[2]), "+f"(d[3])
        : "r"(a[0]), "r"(a[1]), "r"(a[2]), "r"(a[3]), "r"(b0), "r"(b1));
}

// ---------------- CSR build (hist also preconverts Wfc2) ----------------
__global__ void k_hist(const int* __restrict__ edst, const float* __restrict__ Wfc2,
                       int E) {
    int e = blockIdx.x * blockDim.x + threadIdx.x;
    if (e < 16384) g_w2b[e] = __float2bfloat16(Wfc2[e]);
    if (e < E) atomicAdd(&g_deg[edst[e]], 1);
}
#define SCAN_T 1024
__global__ void k_scan(int N) {
    __shared__ int sums[SCAN_T];
    int t = threadIdx.x;
    int IT = (N + SCAN_T - 1) / SCAN_T;
    int lo = t * IT, hi = lo + IT; if (hi > N) hi = N; if (lo > N) lo = N;
    int s = 0;
    for (int i = lo; i < hi; i++) s += g_deg[i];
    sums[t] = s;
    __syncthreads();
    for (int off = 1; off < SCAN_T; off <<= 1) {
        int v = (t >= off) ? sums[t - off] : 0;
        __syncthreads();
        sums[t] += v;
        __syncthreads();
    }
    int run = (t == 0) ? 0 : sums[t - 1];
    for (int i = lo; i < hi; i++) {
        g_rowstart[i] = run;
        g_cursor[i]   = run;
        run += g_deg[i];
    }
    if (hi == N) g_rowstart[N] = run;
}
__global__ void k_fill(const int* __restrict__ esrc, const int* __restrict__ edst, int E) {
    int e = blockIdx.x * blockDim.x + threadIdx.x;
    if (e >= E) return;
    int pos = atomicAdd(&g_cursor[edst[e]], 1);
    g_srcP[pos] = esrc[e];
    g_invP[pos] = e;
}

// ================= device bodies ======================

// --- fctp1: packed f32x2, interleaved weight pairs (64 KB smem) ---
__device__ void fctp1_dev(float* sm, const float* __restrict__ attr,
                          const float* __restrict__ xin,
                          const float* __restrict__ W0, const float* __restrict__ W1,
                          const float* __restrict__ L0, const float* __restrict__ L1,
                          int N, int relBid, int nBlocks) {
    float2* sW02 = (float2*)sm;
    float2* sW12 = (float2*)(sm + 8192);
    for (int i = threadIdx.x; i < 4096; i += 256) {
        sW02[i] = make_float2(W0[i], L0[i]);
        sW12[i] = make_float2(W1[i], L1[i]);
    }
    __syncthreads();
    const ull* w02 = (const ull*)sW02;
    const ull* w12 = (const ull*)sW12;
    int lane = threadIdx.x & 31;
    int wid  = relBid * 8 + (threadIdx.x >> 5);
    int wstr = nBlocks * 8;
    for (int n = wid; n < N; n += wstr) {
        float sl, v0, v1, v2;
        if (xin) {
            sl = xin[n*128 + lane];
            v0 = xin[n*128 + 32 + lane*3 + 0];
            v1 = xin[n*128 + 32 + lane*3 + 1];
            v2 = xin[n*128 + 32 + lane*3 + 2];
            g_s[n*32+lane]      = sl;
            g_v[n*96+lane]      = v0;
            g_v[n*96+32+lane]   = v1;
            g_v[n*96+64+lane]   = v2;
        } else {
            sl = g_s[n*32 + lane];
            v0 = g_v[n*96 + lane];
            v1 = g_v[n*96 + 32 + lane];
            v2 = g_v[n*96 + 64 + lane];
        }
        ull atp[4];
#pragma unroll
        for (int a = 0; a < 4; a++) { float av = attr[n*4+a]; atp[a] = pack2(av, av); }
        ull accS = 0ull, accV0 = 0ull, accV1 = 0ull, accV2 = 0ull;
        for (int u = 0; u < 32; u++) {
            float su  = __shfl_sync(0xffffffffu, sl, u);
            float vu0 = __shfl_sync(0xffffffffu, v0, u);
            float vu1 = __shfl_sync(0xffffffffu, v1, u);
            float vu2 = __shfl_sync(0xffffffffu, v2, u);
            ull sup = pack2(su, su);
            ull v0p = pack2(vu0, vu0);
            ull v1p = pack2(vu1, vu1);
            ull v2p = pack2(vu2, vu2);
            int base = u*128 + lane;
#pragma unroll
            for (int a = 0; a < 4; a++) {
                int wi = base + a*32;
                ull wa = w02[wi];
                ull wb = w12[wi];
                ffma2(accS,  mul2r(sup, atp[a]), wa);
                ffma2(accV0, mul2r(v0p, atp[a]), wb);
                ffma2(accV1, mul2r(v1p, atp[a]), wb);
                ffma2(accV2, mul2r(v2p, atp[a]), wb);
            }
        }
        float2 fS  = unpack2(accS);
        float2 fV0 = unpack2(accV0);
        float2 fV1 = unpack2(accV1);
        float2 fV2 = unpack2(accV2);
        g_scs[n*32+lane] = fS.x*NORM128;
        g_xs [n*32+lane] = fS.y*NORM128;
        g_scv[n*96+lane]      = fV0.x*NORM128;
        g_scv[n*96+32+lane]   = fV1.x*NORM128;
        g_scv[n*96+64+lane]   = fV2.x*NORM128;
        g_xv [n*96+lane]      = fV0.y*NORM128;
        g_xv [n*96+32+lane]   = fV1.y*NORM128;
        g_xv [n*96+64+lane]   = fV2.y*NORM128;
    }
}

// --- wgemm: 128-edge tile; h,W2 bf16 smem; h@W2 on tensor pipe ---
__device__ void wgemm_dev(float* sm, const float* __restrict__ evec,
                          const float* __restrict__ Wfc1, int w2off,
                          __nv_bfloat16* __restrict__ wout, int E, int bid,
                          int writeY) {
    float* shW1  = sm;                              // 640 f
    float* shEmb = sm + 640;                        // 1280 f
    __nv_bfloat16* shW2b = (__nv_bfloat16*)(sm + 1920);
    __nv_bfloat16* shHb  = (__nv_bfloat16*)(sm + 1920 + 4352);
    int tid = threadIdx.x;
    int eg0 = bid * WG_TE;
    int nE = E - eg0; if (nE > WG_TE) nE = WG_TE;

    for (int i = tid; i < 640; i += 256) shW1[i] = Wfc1[i];
    {
        const uint4* src = (const uint4*)(g_w2b + w2off);
        for (int i = tid; i < 1024; i += 256) {
            int k = i >> 4, c = i & 15;
            *(uint4*)&shW2b[k*W2_STR + c*8] = src[i];
        }
    }
    if (tid < WG_TE) {
        if (tid < nE) {
            int p = eg0 + tid;
            int e = g_invP[p];
            float vx = evec[e*3+0], vy = evec[e*3+1], vz = evec[e*3+2];
            float len = sqrtf(vx*vx + vy*vy + vz*vz);
            if (writeY) {
                float inv = 1.0f / (len + 1e-9f);
                g_YP[p*3+0] = SQRT3F * vx * inv;
                g_YP[p*3+1] = SQRT3F * vy * inv;
                g_YP[p*3+2] = SQRT3F * vz * inv;
            }
            float uu = 0.5f*len - 2.0f;
            float cut;
            if (uu > 0.0f)       cut = 0.0f;
            else if (uu < -1.0f) cut = 1.0f;
            else                 cut = (1.0f - __cosf(PI_F * uu)) * 0.5f;
#pragma unroll
            for (int b = 0; b < 10; b++) {
                float c = (4.0f/9.0f) * (float)b;
                float d = (len - c) * 2.5f;
                shEmb[tid*10+b] = __expf(-d*d) * cut;
            }
        } else {
#pragma unroll
            for (int b = 0; b < 10; b++) shEmb[tid*10+b] = 0.f;
        }
    }
    __syncthreads();

    for (int idx = tid; idx < WG_TE*64; idx += 256) {
        int e = idx >> 6, k = idx & 63;
        float acc = 0.f;
#pragma unroll
        for (int b = 0; b < 10; b++) acc += shEmb[e*10+b] * shW1[b*64+k];
        acc *= INVS10;
        shHb[e*HB_STR + k] = __float2bfloat16(acc / (1.0f + __expf(-acc)));
    }
    __syncthreads();

    int lane = tid & 31;
    int warp = tid >> 5;
    int eb = (warp & 3) * 32;
    int nb = (warp >> 2) * 64;

    unsigned a[2][4][4];
    {
        int r  = lane & 15;
        int cA = (lane >> 4) << 3;
#pragma unroll
        for (int mt = 0; mt < 2; mt++)
#pragma unroll
            for (int kc = 0; kc < 4; kc++) {
                unsigned ad = sptr(&shHb[(eb + mt*16 + r)*HB_STR + kc*16 + cA]);
                asm volatile(
                    "ldmatrix.sync.aligned.m8n8.x4.shared.b16 {%0,%1,%2,%3}, [%4];"
                    : "=r"(a[mt][kc][0]), "=r"(a[mt][kc][1]),
                      "=r"(a[mt][kc][2]), "=r"(a[mt][kc][3])
                    : "r"(ad));
            }
    }

    int row  = lane >> 2;
    int colp = (lane & 3) * 2;
#pragma unroll
    for (int nt = 0; nt < 8; nt++) {
        float acc0[4] = {0.f, 0.f, 0.f, 0.f};
        float acc1[4] = {0.f, 0.f, 0.f, 0.f};
#pragma unroll
        for (int kc = 0; kc < 4; kc++) {
            int rk = lane & 15;
            unsigned bd = sptr(&shW2b[(kc*16 + rk)*W2_STR + nb + nt*8]);
            unsigned b0, b1;
            asm volatile(
                "ldmatrix.sync.aligned.m8n8.x2.trans.shared.b16 {%0,%1}, [%2];"
                : "=r"(b0), "=r"(b1) : "r"(bd));
            mma16816(acc0, a[0][kc], b0, b1);
            mma16816(acc1, a[1][kc], b0, b1);
        }
        int col = nb + nt*8 + colp;
        int geA = eg0 + eb + row;
        int geB = geA + 8;
        int geC = geA + 16;
        int geD = geA + 24;
        if (geA < E)
            *(unsigned*)&wout[(size_t)geA*128 + col] = bf16x2_of(acc0[0]*0.125f, acc0[1]*0.125f);
        if (geB < E)
            *(unsigned*)&wout[(size_t)geB*128 + col] = bf16x2_of(acc0[2]*0.125f, acc0[3]*0.125f);
        if (geC < E)
            *(unsigned*)&wout[(size_t)geC*128 + col] = bf16x2_of(acc1[0]*0.125f, acc1[1]*0.125f);
        if (geD < E)
            *(unsigned*)&wout[(size_t)geD*128 + col] = bf16x2_of(acc1[2]*0.125f, acc1[3]*0.125f);
    }
}

// --- fctp2: packed f32x2 + gated state update (64 KB smem) ---
__device__ void fctp2_dev(float* sm, const float* __restrict__ attr,
                          const float* __restrict__ W20, const float* __restrict__ W21,
                          int N, int relBid, int nBlocks) {
    float2* sWp = (float2*)sm;
    for (int i = threadIdx.x; i < 8192; i += 256)
        sWp[i] = make_float2(W20[i], W21[i]);
    __syncthreads();
    const ull* wPair = (const ull*)sWp;
    int lane = threadIdx.x & 31;
    int wid  = relBid * 8 + (threadIdx.x >> 5);
    int wstr = nBlocks * 8;
    for (int n = wid; n < N; n += wstr) {
        float sa  = g_aggs[n*64 + lane],        sb  = g_aggs[n*64 + 32 + lane];
        float va0 = g_aggv[n*192 + lane],       vb0 = g_aggv[n*192 + 32 + lane];
        float va1 = g_aggv[n*192 + 64 + lane],  vb1 = g_aggv[n*192 + 96 + lane];
        float va2 = g_aggv[n*192 + 128 + lane], vb2 = g_aggv[n*192 + 160 + lane];
        ull atp[4];
#pragma unroll
        for (int a = 0; a < 4; a++) { float av = attr[n*4+a]; atp[a] = pack2(av, av); }
        ull accA = 0ull;
        ull accB = 0ull;
#pragma unroll 1
        for (int half = 0; half < 2; half++) {
            float ss  = half ? sb  : sa;
            float vv0 = half ? vb0 : va0;
            float vv1 = half ? vb1 : va1;
            float vv2 = half ? vb2 : va2;
            int uoff = half ? 32 : 0;
            for (int u = 0; u < 32; u++) {
                float su = __shfl_sync(0xffffffffu, ss,  u);
                float w0 = __shfl_sync(0xffffffffu, vv0, u);
                float w1 = __shfl_sync(0xffffffffu, vv1, u);
                float w2 = __shfl_sync(0xffffffffu, vv2, u);
                ull pA = pack2(su, w2);
                ull pB = pack2(w0, w1);
                int base = (u + uoff)*128 + lane;
#pragma unroll
                for (int a = 0; a < 4; a++) {
                    int wi = base + a*32;
                    ull wp = wPair[wi];
                    float2 wf = unpack2(wp);
                    ull wdup = pack2(wf.y, wf.y);
                    ffma2(accA, mul2r(pA, atp[a]), wp);
                    ffma2(accB, mul2r(pB, atp[a]), wdup);
                }
            }
        }
        float2 fA = unpack2(accA);
        float2 fB = unpack2(accB);
        float os  = fA.x*NORM256, ov2 = fA.y*NORM256;
        float ov0 = fB.x*NORM256, ov1 = fB.y*NORM256;
        float sn  = C_S * g_scs[n*32+lane] + C_X * os;
        float sig = 1.0f / (1.0f + __expf(-sn));
        g_s[n*32+lane] += sn * sig;
        float vn0 = C_S * g_scv[n*96+lane]      + C_X * ov0;
        float vn1 = C_S * g_scv[n*96+32+lane]   + C_X * ov1;
        float vn2 = C_S * g_scv[n*96+64+lane]   + C_X * ov2;
        g_v[n*96+lane]      += vn0 * sig;
        g_v[n*96+32+lane]   += vn1 * sig;
        g_v[n*96+64+lane]   += vn2 * sig;
    }
}

// ================= gather: dual independent edge streams (fp32 features) =====
template<int BUF>
__global__ void __launch_bounds__(256)
k_gather(int N) {
    const __nv_bfloat16* __restrict__ win = BUF ? g_wb1 : g_wb0;
    int tid = threadIdx.x;
    int n = blockIdx.x*2 + (tid >> 7);
    if (n >= N) return;
    int sub = tid & 127;
    int k = sub >> 5, u = sub & 31;
    int t0 = g_rowstart[n], t1 = g_rowstart[n+1];
    int len  = t1 - t0;
    int hlen = (len + 1) >> 1;
    int tB0  = t0 + hlen;
    float a0 = 0.f, a1 = 0.f, a2 = 0.f;
    float b0 = 0.f, b1 = 0.f, b2 = 0.f;

    if (k == 0) {
        for (int i = 0; i < hlen; i++) {
            int eA = t0 + i, eB = tB0 + i;
            bool vB = (eB < t1);
            int sA = g_srcP[eA];
            int sB = vB ? g_srcP[eB] : 0;
            float wA = __bfloat162float(win[(size_t)eA*128 + u]);
            float wB = vB ? __bfloat162float(win[(size_t)eB*128 + u]) : 0.f;
            a0 += wA * g_xs[sA*32 + u];
            b0 += wB * g_xs[sB*32 + u];
        }
        g_aggs[n*64 + u] = (a0 + b0) * INV_NB;
    } else if (k == 1) {
        for (int i = 0; i < hlen; i++) {
            int eA = t0 + i, eB = tB0 + i;
            bool vB = (eB < t1);
            int sA = g_srcP[eA];
            int sB = vB ? g_srcP[eB] : 0;
            float wA = __bfloat162float(win[(size_t)eA*128 + 32 + u]);
            float wB = vB ? __bfloat162float(win[(size_t)eB*128 + 32 + u]) : 0.f;
            float dA = g_YP[eA*3+0]*g_xv[sA*96+u] + g_YP[eA*3+1]*g_xv[sA*96+32+u]
                     + g_YP[eA*3+2]*g_xv[sA*96+64+u];
            float dB = g_YP[eB < t1 ? eB*3+0 : 0]*g_xv[sB*96+u]
                     + g_YP[eB < t1 ? eB*3+1 : 0]*g_xv[sB*96+32+u]
                     + g_YP[eB < t1 ? eB*3+2 : 0]*g_xv[sB*96+64+u];
            a0 += wA * dA;
            b0 += wB * dB;
        }
        g_aggs[n*64 + 32 + u] = (a0 + b0) * ISQRT3F * INV_NB;
    } else if (k == 2) {
        for (int i = 0; i < hlen; i++) {
            int eA = t0 + i, eB = tB0 + i;
            bool vB = (eB < t1);
            int sA = g_srcP[eA];
            int sB = vB ? g_srcP[eB] : 0;
            float wA = __bfloat162float(win[(size_t)eA*128 + 64 + u]);
            float wB = vB ? __bfloat162float(win[(size_t)eB*128 + 64 + u]) : 0.f;
            float mA = wA * g_xs[sA*32 + u];
            float mB = wB * g_xs[sB*32 + u];
            a0 += mA * g_YP[eA*3+0];
            a1 += mA * g_YP[eA*3+1];
            a2 += mA * g_YP[eA*3+2];
            int eBs = vB ? eB : eA;
            b0 += mB * g_YP[eBs*3+0];
            b1 += mB * g_YP[eBs*3+1];
            b2 += mB * g_YP[eBs*3+2];
        }
        g_aggv[n*192 +       u] = (a0 + b0) * INV_NB;
        g_aggv[n*192 +  64 + u] = (a1 + b1) * INV_NB;
        g_aggv[n*192 + 128 + u] = (a2 + b2) * INV_NB;
    } else {
        for (int i = 0; i < hlen; i++) {
            int eA = t0 + i, eB = tB0 + i;
            bool vB = (eB < t1);
            int sA = g_srcP[eA];
            int sB = vB ? g_srcP[eB] : 0;
            float wA = __bfloat162float(win[(size_t)eA*128 + 96 + u]);
            float wB = vB ? __bfloat162float(win[(size_t)eB*128 + 96 + u]) : 0.f;
            a0 += wA * g_xv[sA*96 + u];
            a1 += wA * g_xv[sA*96 + 32 + u];
            a2 += wA * g_xv[sA*96 + 64 + u];
            b0 += wB * g_xv[sB*96 + u];
            b1 += wB * g_xv[sB*96 + 32 + u];
            b2 += wB * g_xv[sB*96 + 64 + u];
        }
        g_aggv[n*192 +  32 + u] = (a0 + b0) * INV_NB;
        g_aggv[n*192 +  96 + u] = (a1 + b1) * INV_NB;
        g_aggv[n*192 + 160 + u] = (a2 + b2) * INV_NB;
    }
}

// ================= launches ======================

__global__ void __launch_bounds__(256, 3)
k_fusedA(const float* __restrict__ attr, const float* __restrict__ x,
         const float* __restrict__ evec,
         const float* __restrict__ W0, const float* __restrict__ W1,
         const float* __restrict__ L0, const float* __restrict__ L1,
         const float* __restrict__ Wfc1,
         int N, int E, int nWG, int nFC) {
    extern __shared__ float sm[];
    if ((int)blockIdx.x < nWG) wgemm_dev(sm, evec, Wfc1, 0, g_wb0, E, blockIdx.x, 1);
    else fctp1_dev(sm, attr, x, W0, W1, L0, L1, N, blockIdx.x - nWG, nFC);
}

__global__ void __launch_bounds__(256, 3)
k_fusedC(const float* __restrict__ attr, const float* __restrict__ evec,
         const float* __restrict__ W20, const float* __restrict__ W21,
         const float* __restrict__ W0b, const float* __restrict__ W1b,
         const float* __restrict__ L0b, const float* __restrict__ L1b,
         const float* __restrict__ Wfc1,
         int N, int E, int nWG, int nFC) {
    extern __shared__ float sm[];
    if ((int)blockIdx.x < nWG) {
        wgemm_dev(sm, evec, Wfc1, 8192, g_wb1, E, blockIdx.x, 0);
    } else {
        int rb = blockIdx.x - nWG;
        fctp2_dev(sm, attr, W20, W21, N, rb, nFC);
        __syncthreads();
        fctp1_dev(sm, attr, nullptr, W0b, W1b, L0b, L1b, N, rb, nFC);
    }
}

// --- fctp2(L1) fused with readout + pooling; also restores g_deg=0 ---
__global__ void __launch_bounds__(256, 3)
k_fctp2read(const float* __restrict__ attr, const int* __restrict__ batch,
            const float* __restrict__ W20, const float* __restrict__ W21,
            const float* __restrict__ Wread, float* __restrict__ out,
            int N, float poolscale) {
    extern __shared__ float sm[];
    float2* sWp  = (float2*)sm;          // 8192 pairs = 64 KB
    float*  shW  = sm + 16384;           // 2048 floats (Wread)
    float*  pool = sm + 18432;           // 128 floats
    for (int i = blockIdx.x * blockDim.x + threadIdx.x; i < N;
         i += gridDim.x * blockDim.x)
        g_deg[i] = 0;
    for (int i = threadIdx.x; i < 8192; i += 256)
        sWp[i] = make_float2(W20[i], W21[i]);
    for (int i = threadIdx.x; i < 2048; i += 256) shW[i] = Wread[i];
    if (threadIdx.x < 128) pool[threadIdx.x] = 0.0f;
    __syncthreads();
    const ull* wPair = (const ull*)sWp;
    int lane = threadIdx.x & 31;
    int wid  = blockIdx.x * 8 + (threadIdx.x >> 5);
    int wstr = gridDim.x * 8;
    int w16  = lane & 15;
    for (int n = wid; n < N; n += wstr) {
        float sa  = g_aggs[n*64 + lane],        sb  = g_aggs[n*64 + 32 + lane];
        float va0 = g_aggv[n*192 + lane],       vb0 = g_aggv[n*192 + 32 + lane];
        float va1 = g_aggv[n*192 + 64 + lane],  vb1 = g_aggv[n*192 + 96 + lane];
        float va2 = g_aggv[n*192 + 128 + lane], vb2 = g_aggv[n*192 + 160 + lane];
        float at0 = attr[n*4+0], at1 = attr[n*4+1], at2 = attr[n*4+2], at3 = attr[n*4+3];
        ull atp[4] = {pack2(at0, at0), pack2(at1, at1), pack2(at2, at2), pack2(at3, at3)};
        ull accA = 0ull;   // {os, ov2} (ov2 unused for readout but cheap)
        ull accB = 0ull;
#pragma unroll 1
        for (int half = 0; half < 2; half++) {
            float ss  = half ? sb  : sa;
            float vv0 = half ? vb0 : va0;
            float vv1 = half ? vb1 : va1;
            float vv2 = half ? vb2 : va2;
            int uoff = half ? 32 : 0;
            for (int u = 0; u < 32; u++) {
                float su = __shfl_sync(0xffffffffu, ss,  u);
                float w0 = __shfl_sync(0xffffffffu, vv0, u);
                float w1 = __shfl_sync(0xffffffffu, vv1, u);
                float w2 = __shfl_sync(0xffffffffu, vv2, u);
                ull pA = pack2(su, w2);
                ull pB = pack2(w0, w1);
                int base = (u + uoff)*128 + lane;
#pragma unroll
                for (int a = 0; a < 4; a++) {
                    int wi = base + a*32;
                    ull wp = wPair[wi];
                    float2 wf = unpack2(wp);
                    ull wdup = pack2(wf.y, wf.y);
                    ffma2(accA, mul2r(pA, atp[a]), wp);
                    ffma2(accB, mul2r(pB, atp[a]), wdup);
                }
            }
        }
        float2 fA = unpack2(accA);
        float os  = fA.x*NORM256;
        float sn  = C_S * g_scs[n*32+lane] + C_X * os;
        float sig = 1.0f / (1.0f + __expf(-sn));
        float snew = g_s[n*32+lane] + sn * sig;
        // readout: acc[w16] = sum_u snew[u] * sum_a attr[a]*Wread[u,a,w16]
        float acc = 0.f;
        for (int u = 0; u < 32; u++) {
            float su = __shfl_sync(0xffffffffu, snew, u);
            int base = u*64 + w16;
            acc += su*(at0*shW[base] + at1*shW[base+16] + at2*shW[base+32] + at3*shW[base+48]);
        }
        if (lane < 16) {
            int g = batch[n];
            atomicAdd(&pool[g*16 + w16], acc * NORM128 * poolscale);
        }
    }
    __syncthreads();
    if (threadIdx.x < 128) atomicAdd(&out[threadIdx.x], pool[threadIdx.x]);
}

__global__ void k_zero_out(float* out) { out[threadIdx.x] = 0.0f; }

// ---------------- launcher ----------------
extern "C" void kernel_launch(void* const* d_in, const int* in_sizes, int n_in,
                              void* d_out, int out_size) {
    const float* x    = (const float*)d_in[0];
    const float* attr = (const float*)d_in[1];
    const float* evec = (const float*)d_in[2];
    const int*   batch= (const int*)  d_in[3];
    const int*   esrc = (const int*)  d_in[4];
    const int*   edst = (const int*)  d_in[5];
    const float* Wsc0 = (const float*)d_in[6];
    const float* Wsc1 = (const float*)d_in[7];
    const float* Wl10 = (const float*)d_in[8];
    const float* Wl11 = (const float*)d_in[9];
    const float* Wfc1 = (const float*)d_in[10];
    const float* Wfc2 = (const float*)d_in[11];
    const float* Wl20 = (const float*)d_in[12];
    const float* Wl21 = (const float*)d_in[13];
    const float* Wread= (const float*)d_in[14];
    int N = in_sizes[0] / 128;
    int E = in_sizes[4];

    cudaFuncSetAttribute(k_fusedA,    cudaFuncAttributeMaxDynamicSharedMemorySize, FUSED_SMEM);
    cudaFuncSetAttribute(k_fusedC,    cudaFuncAttributeMaxDynamicSharedMemorySize, FUSED_SMEM);
    cudaFuncSetAttribute(k_fctp2read, cudaFuncAttributeMaxDynamicSharedMemorySize, READ_SMEM);

    int nWG = (E + WG_TE - 1) / WG_TE;
    int nFC = 444;
    int nGB = (N + 1) / 2;

    // CSR build (+W2 preconvert inside hist)
    k_hist<<<(E + 255) / 256, 256>>>(edst, Wfc2, E);
    k_scan<<<1, SCAN_T>>>(N);
    k_fill<<<(E + 255) / 256, 256>>>(esrc, edst, E);

    // layer 0 (+ hidden wgemm(L1) and fctp1(L1))
    k_fusedA<<<nWG + nFC, 256, FUSED_SMEM>>>(attr, x, evec,
                                             Wsc0, Wsc1, Wl10, Wl11,
                                             Wfc1, N, E, nWG, nFC);
    k_gather<0><<<nGB, 256>>>(N);
    k_fusedC<<<nWG + nFC, 256, FUSED_SMEM>>>(attr, evec, Wl20, Wl21,
                                             Wsc0 + 4096, Wsc1 + 4096,
                                             Wl10 + 4096, Wl11 + 4096,
                                             Wfc1 + 640, N, E, nWG, nFC);
    // layer 1 tail: gather, then fctp2+readout fused
    k_gather<1><<<nGB, 256>>>(N);
    k_zero_out<<<1, 128>>>((float*)d_out);
    float poolscale = 1.0f / sqrtf((float)N / 8.0f);
    k_fctp2read<<<444, 256, READ_SMEM>>>(attr, batch, Wl20 + 8192, Wl21 + 8192,
                                         Wread, (float*)d_out, N, poolscale);
}